// round 13
// baseline (speedup 1.0000x reference)
#include <cuda_runtime.h>
#include <cuda_fp16.h>
#include <cstdint>

#define T_   128
#define A_   8
#define CSZ  8
#define NCL  16

#define OFF_W0  0        // 128x256 fp16 swizzled (64KB)
#define OFF_W1  65536    // 128x512 fp16 swizzled (128KB)
#define OFF_FCW 196608   // 256 f32
#define OFF_B1  197632   // 128 f32
#define SMEMB   198144

__device__ __half g_W0img[CSZ * 128 * 256];
__device__ __half g_W1img[CSZ * 128 * 512];
__device__ __half g_hcat[2 * NCL * 64 * 512];   // [par][cid][row][h0|h1]
__device__ float  g_gx0[1024 * 1024];           // [b][unit*4+gate]
__device__ float  g_b1s[CSZ * 128];

// ---------------- helpers ---------------------------------------------------
__device__ __forceinline__ uint32_t s2u(const void* p) {
    uint32_t a;
    asm("{ .reg .u64 t; cvta.to.shared.u64 t, %1; cvt.u32.u64 %0, t; }"
        : "=r"(a) : "l"(p));
    return a;
}
__device__ __forceinline__ uint32_t crank() {
    uint32_t r; asm("mov.u32 %0, %%cluster_ctarank;" : "=r"(r)); return r;
}
__device__ __forceinline__ void csync() {
    asm volatile("barrier.cluster.arrive.aligned;" ::: "memory");
    asm volatile("barrier.cluster.wait.aligned;" ::: "memory");
}
__device__ __forceinline__ float tap(float x) {
    float y; asm("tanh.approx.f32 %0, %1;" : "=f"(y) : "f"(x)); return y;
}
__device__ __forceinline__ float sg(float x) {
    return fmaf(tap(0.5f * x), 0.5f, 0.5f);
}
__device__ __forceinline__ void ldsm4(uint32_t (&d)[4], uint32_t addr) {
    asm volatile("ldmatrix.sync.aligned.m8n8.x4.shared.b16 {%0,%1,%2,%3}, [%4];"
        : "=r"(d[0]), "=r"(d[1]), "=r"(d[2]), "=r"(d[3]) : "r"(addr));
}
__device__ __forceinline__ void hmma(float (&c)[4], const uint32_t (&a)[4],
                                     uint32_t b0, uint32_t b1) {
    asm volatile(
        "mma.sync.aligned.m16n8k16.row.col.f32.f16.f16.f32 "
        "{%0,%1,%2,%3}, {%4,%5,%6,%7}, {%8,%9}, {%0,%1,%2,%3};"
        : "+f"(c[0]), "+f"(c[1]), "+f"(c[2]), "+f"(c[3])
        : "r"(a[0]), "r"(a[1]), "r"(a[2]), "r"(a[3]), "r"(b0), "r"(b1));
}
__device__ __forceinline__ uint32_t ldcg(const uint32_t* p) {
    uint32_t v;
    asm volatile("ld.global.cg.b32 %0, [%1];" : "=r"(v) : "l"(p));
    return v;
}
__device__ __forceinline__ uint4 ldcg4(const uint4* p) {
    uint4 v;
    asm volatile("ld.global.cg.v4.b32 {%0,%1,%2,%3}, [%4];"
        : "=r"(v.x), "=r"(v.y), "=r"(v.z), "=r"(v.w) : "l"(p));
    return v;
}
__device__ __forceinline__ void stcg16(__half* p, __half v) {
    unsigned short u = __half_as_ushort(v);
    asm volatile("st.global.cg.u16 [%0], %1;" :: "l"(p), "h"(u));
}

// ============================================================================
__global__ void prep_weights(const float* __restrict__ Whh0,
                             const float* __restrict__ Wih1,
                             const float* __restrict__ Whh1,
                             const float* __restrict__ bih1,
                             const float* __restrict__ bhh1)
{
    const int idx = blockIdx.x * blockDim.x + threadIdx.x;
    const int str = gridDim.x * blockDim.x;
    for (int i = idx; i < CSZ * 128 * 256; i += str) {
        const int rk = i >> 15, n = (i >> 8) & 127, k = i & 255;
        const int no = (n & 3) * 256 + rk * 32 + (n >> 2);
        g_W0img[(rk << 15) + (n << 8) + (k ^ ((n & 7) << 3))] =
            __float2half(Whh0[no * 256 + k]);
    }
    for (int i = idx; i < CSZ * 128 * 512; i += str) {
        const int rk = i >> 16, n = (i >> 9) & 127, k = i & 511;
        const int no = (n & 3) * 256 + rk * 32 + (n >> 2);
        const float v = (k < 256) ? Wih1[no * 256 + k]
                                  : Whh1[no * 256 + (k - 256)];
        g_W1img[(rk << 16) + (n << 9) + (k ^ ((n & 7) << 3))] = __float2half(v);
    }
    for (int i = idx; i < CSZ * 128; i += str) {
        const int rk = i >> 7, cc = i & 127;
        const int no = (cc & 3) * 256 + rk * 32 + (cc >> 2);
        g_b1s[i] = bih1[no] + bhh1[no];
    }
    for (int i = idx; i < 2 * NCL * 64 * 512; i += str)
        g_hcat[i] = __half(0.0f);
}

__global__ void prep_gx0(const float* __restrict__ state,
                         const float* __restrict__ gamma,
                         const float* __restrict__ beta,
                         const float* __restrict__ Wih0,
                         const float* __restrict__ bih0,
                         const float* __restrict__ bhh0)
{
    const int b = blockIdx.x, t = threadIdx.x;
    __shared__ float xs[64], xn[64];
    if (t < 64) xs[t] = state[b * 64 + t];
    __syncthreads();
    float mu = 0.f;
    #pragma unroll
    for (int k = 0; k < 64; k++) mu += xs[k];
    mu *= (1.0f / 64.0f);
    float var = 0.f;
    #pragma unroll
    for (int k = 0; k < 64; k++) { float d = xs[k] - mu; var += d * d; }
    const float rs = rsqrtf(var * (1.0f / 64.0f) + 1e-5f);
    if (t < 64) xn[t] = (xs[t] - mu) * rs * gamma[t] + beta[t];
    __syncthreads();
    #pragma unroll
    for (int g = 0; g < 4; g++) {
        const int n = g * 256 + t;
        const float* w = Wih0 + n * 64;
        float acc = bih0[n] + bhh0[n];
        #pragma unroll
        for (int k = 0; k < 64; k++) acc += xn[k] * w[k];
        g_gx0[b * 1024 + t * 4 + g] = acc;
    }
}

// ============================================================================
// 16 clusters x 8 CTAs x 256 thr. h state lives in parity-buffered L2 gmem;
// A-frags via ld.cg, B-frags via ldmatrix from SMEM-resident fp16 weights.
// 2 cluster barriers/step, no syncthreads, no membar. Single-writer + parity.
// ============================================================================
__global__ void __launch_bounds__(256, 1) __cluster_dims__(CSZ, 1, 1)
lstm_mma(const float* __restrict__ fcW, const float* __restrict__ fcb,
         float* __restrict__ out)
{
    extern __shared__ char sm[];
    float* sfcw = (float*)(sm + OFF_FCW);
    float* sb1  = (float*)(sm + OFF_B1);
    const uint32_t w0sm = s2u(sm) + OFF_W0;
    const uint32_t w1sm = s2u(sm) + OFF_W1;

    const int tid = threadIdx.x, wid = tid >> 5, lane = tid & 31;
    const int mt = wid & 3, ch = wid >> 2;
    const uint32_t rank = crank();
    const int cid = blockIdx.x >> 3;

    {   // stage weights + constants into smem
        const uint4* s0 = (const uint4*)(g_W0img + ((uint32_t)rank << 15));
        const uint4* s1 = (const uint4*)(g_W1img + ((uint32_t)rank << 16));
        uint4* d0 = (uint4*)sm;
        uint4* d1 = (uint4*)(sm + OFF_W1);
        for (int i = tid; i < 4096; i += 256) d0[i] = s0[i];
        for (int i = tid; i < 8192; i += 256) d1[i] = s1[i];
        for (int i = tid; i < 256; i += 256) sfcw[i] = fcW[rank * 256 + i];
        if (tid < 128) sb1[tid] = g_b1s[rank * 128 + tid];
    }
    const float fcbv = fcb[rank];

    // cell geometry (identical to passing R12)
    const int cellrow = mt * 16 + (lane >> 2) + ((lane & 1) << 3);
    const int uloc0 = ch * 16 + ((lane >> 1) & 1);
    float4 gx[8];
    #pragma unroll
    for (int t = 0; t < 8; t++)
        gx[t] = *(const float4*)(g_gx0 + (cid * 64 + cellrow) * 1024 +
                                 ((int)rank * 32 + uloc0 + 2 * t) * 4);
    float c0r[8], c1r[8];
    #pragma unroll
    for (int t = 0; t < 8; t++) { c0r[t] = 0.f; c1r[t] = 0.f; }

    // A-frag / B-frag lane geometry
    const int arow = mt * 16 + (lane >> 2);
    const int ac   = lane & 3;
    const int nb = ch * 64 + ((lane >> 4) & 1) * 8 + (lane & 7);
    const uint32_t xkB = (uint32_t)(((lane >> 3) & 1) << 4);
    // FC geometry
    const int lr = tid >> 2, lseg = tid & 3;

    const uint32_t* hbase = (const uint32_t*)g_hcat;   // u32 view, row=256 u32
    __half* hraw = g_hcat;

    __syncthreads();   // smem staging visible CTA-wide

    float acc[8][4];
    for (int s = 0; s < T_; s++) {
        const int pw = s & 1, pr = pw ^ 1;
        const uint32_t rbR = ((uint32_t)(pr * NCL + cid) * 64 + arow) * 256;
        const uint32_t rbW = ((uint32_t)(pw * NCL + cid) * 64 + arow) * 256;

        // ---------------- L0: gates0 = h0(s-1) @ W0 ------------------------
        #pragma unroll
        for (int t = 0; t < 8; t++)
            { acc[t][0]=0.f; acc[t][1]=0.f; acc[t][2]=0.f; acc[t][3]=0.f; }
        {
            const uint32_t* p0 = hbase + rbR + ac;
            const uint32_t* p1 = p0 + 8 * 256;
            #pragma unroll 4
            for (int kb = 0; kb < 16; kb++) {
                uint32_t a[4];
                a[0] = ldcg(p0 + kb * 8);
                a[1] = ldcg(p1 + kb * 8);
                a[2] = ldcg(p0 + kb * 8 + 4);
                a[3] = ldcg(p1 + kb * 8 + 4);
                #pragma unroll
                for (int nt = 0; nt < 4; nt++) {
                    const int n = nb + nt * 16;
                    uint32_t b[4];
                    ldsm4(b, w0sm + ((uint32_t)n << 9) +
                             (((uint32_t)(kb * 32) + xkB) ^
                              (uint32_t)((n & 7) << 4)));
                    hmma(acc[2 * nt],     a, b[0], b[1]);
                    hmma(acc[2 * nt + 1], a, b[2], b[3]);
                }
            }
        }
        // cell0 -> store h0(s) fragment
        {
            __half* hst = hraw + ((size_t)(pw * NCL + cid) * 64 + cellrow) * 512
                          + (int)rank * 32 + uloc0;
            #pragma unroll
            for (int t = 0; t < 8; t++) {
                const float s0 = __shfl_xor_sync(0xffffffffu, acc[t][0], 1);
                const float s1 = __shfl_xor_sync(0xffffffffu, acc[t][1], 1);
                const float s2 = __shfl_xor_sync(0xffffffffu, acc[t][2], 1);
                const float s3 = __shfl_xor_sync(0xffffffffu, acc[t][3], 1);
                float gi, gf, gg, go;
                if (lane & 1) { gi = s2; gf = s3; gg = acc[t][2]; go = acc[t][3]; }
                else          { gi = acc[t][0]; gf = acc[t][1]; gg = s0; go = s1; }
                gi += gx[t].x; gf += gx[t].y; gg += gx[t].z; go += gx[t].w;
                const float cn = sg(gf) * c0r[t] + sg(gi) * tap(gg);
                c0r[t] = cn;
                stcg16(hst + 2 * t, __float2half(sg(go) * tap(cn)));
            }
        }
        csync();   // h0(s) visible cluster-wide (arrive=release, wait=acquire)

        // ---------------- L1: gates1 = [h0(s) | h1(s-1)] @ W1 ---------------
        #pragma unroll
        for (int t = 0; t < 8; t++)
            { acc[t][0]=0.f; acc[t][1]=0.f; acc[t][2]=0.f; acc[t][3]=0.f; }
        {
            const uint32_t* q0 = hbase + rbW + ac;            // h0 new
            const uint32_t* q1 = q0 + 8 * 256;
            const uint32_t* r0 = hbase + rbR + 128 + ac;      // h1 old
            const uint32_t* r1 = r0 + 8 * 256;
            #pragma unroll 4
            for (int kb = 0; kb < 32; kb++) {
                const uint32_t* f0 = (kb < 16) ? q0 : r0;
                const uint32_t* f1 = (kb < 16) ? q1 : r1;
                const int kk = kb & 15;
                uint32_t a[4];
                a[0] = ldcg(f0 + kk * 8);
                a[1] = ldcg(f1 + kk * 8);
                a[2] = ldcg(f0 + kk * 8 + 4);
                a[3] = ldcg(f1 + kk * 8 + 4);
                #pragma unroll
                for (int nt = 0; nt < 4; nt++) {
                    const int n = nb + nt * 16;
                    uint32_t b[4];
                    ldsm4(b, w1sm + ((uint32_t)n << 10) +
                             (((uint32_t)(kb * 32) + xkB) ^
                              (uint32_t)((n & 7) << 4)));
                    hmma(acc[2 * nt],     a, b[0], b[1]);
                    hmma(acc[2 * nt + 1], a, b[2], b[3]);
                }
            }
        }
        // cell1 -> store h1(s) fragment
        {
            __half* hst = hraw + ((size_t)(pw * NCL + cid) * 64 + cellrow) * 512
                          + 256 + (int)rank * 32 + uloc0;
            #pragma unroll
            for (int t = 0; t < 8; t++) {
                const float s0 = __shfl_xor_sync(0xffffffffu, acc[t][0], 1);
                const float s1 = __shfl_xor_sync(0xffffffffu, acc[t][1], 1);
                const float s2 = __shfl_xor_sync(0xffffffffu, acc[t][2], 1);
                const float s3 = __shfl_xor_sync(0xffffffffu, acc[t][3], 1);
                float gi, gf, gg, go;
                if (lane & 1) { gi = s2; gf = s3; gg = acc[t][2]; go = acc[t][3]; }
                else          { gi = acc[t][0]; gf = acc[t][1]; gg = s0; go = s1; }
                const float4 bv = *(const float4*)(sb1 + (uloc0 + 2 * t) * 4);
                gi += bv.x; gf += bv.y; gg += bv.z; go += bv.w;
                const float cn = sg(gf) * c1r[t] + sg(gi) * tap(gg);
                c1r[t] = cn;
                stcg16(hst + 2 * t, __float2half(sg(go) * tap(cn)));
            }
        }
        csync();   // h1(s) visible cluster-wide

        // ---------------- FC: action(s) = tanh(h1(s) @ fcW[rank] + b) -------
        {
            const uint4* hp = (const uint4*)(hraw +
                ((size_t)(pw * NCL + cid) * 64 + lr) * 512 + 256 + lseg * 64);
            float f = 0.f;
            #pragma unroll
            for (int i = 0; i < 8; i++) {
                const uint4 v = ldcg4(hp + i);
                const __half2* h2p = (const __half2*)&v;
                #pragma unroll
                for (int j = 0; j < 4; j++) {
                    const float2 h2 = __half22float2(h2p[j]);
                    const int kk = lseg * 64 + i * 8 + 2 * j;
                    f += h2.x * sfcw[kk] + h2.y * sfcw[kk + 1];
                }
            }
            f += __shfl_xor_sync(0xffffffffu, f, 1);
            f += __shfl_xor_sync(0xffffffffu, f, 2);
            if ((tid & 3) == 0)
                out[((cid * 64 + lr) * T_ + s) * A_ + rank] = tap(f + fcbv);
        }
    }
}

// ============================================================================
extern "C" void kernel_launch(void* const* d_in, const int* in_sizes, int n_in,
                              void* d_out, int out_size)
{
    const float* state = (const float*)d_in[0];
    const float* gamma = (const float*)d_in[1];
    const float* beta  = (const float*)d_in[2];
    const float* Wih0  = (const float*)d_in[3];
    const float* Whh0  = (const float*)d_in[4];
    const float* bih0  = (const float*)d_in[5];
    const float* bhh0  = (const float*)d_in[6];
    const float* Wih1  = (const float*)d_in[7];
    const float* Whh1  = (const float*)d_in[8];
    const float* bih1  = (const float*)d_in[9];
    const float* bhh1  = (const float*)d_in[10];
    const float* fcW   = (const float*)d_in[11];
    const float* fcb   = (const float*)d_in[12];
    float* out = (float*)d_out;

    cudaFuncSetAttribute(lstm_mma, cudaFuncAttributeMaxDynamicSharedMemorySize,
                         SMEMB);
    prep_weights<<<264, 256>>>(Whh0, Wih1, Whh1, bih1, bhh1);
    prep_gx0<<<1024, 256>>>(state, gamma, beta, Wih0, bih0, bhh0);
    lstm_mma<<<NCL * CSZ, 256, SMEMB>>>(fcW, fcb, out);
}

// round 14
// speedup vs baseline: 1.1040x; 1.1040x over previous
#include <cuda_runtime.h>
#include <cuda_fp16.h>
#include <cstdint>

#define T_   128
#define A_   8
#define CSZ  8
#define NCL  16
#define NTH  512
#define HTOT (NCL * 64 * 256)

#define OFF_W0  0        // 128x256 fp16 swizzled (64KB)
#define OFF_W1  65536    // 128x512 fp16 swizzled (128KB)
#define OFF_H   196608   // 64x256 fp16 swizzled  (32KB)
#define OFF_FCW 229376   // 256 f32
#define OFF_B1  230400   // 128 f32
#define SMEMB   230912

__device__ __half g_W0img[CSZ * 128 * 256];
__device__ __half g_W1img[CSZ * 128 * 512];
__device__ __half g_h0[HTOT];
__device__ __half g_h1[2 * HTOT];
__device__ float  g_gx0[1024 * 1024];
__device__ float  g_b1s[CSZ * 128];

// ---------------- helpers ---------------------------------------------------
__device__ __forceinline__ uint32_t s2u(const void* p) {
    uint32_t a;
    asm("{ .reg .u64 t; cvta.to.shared.u64 t, %1; cvt.u32.u64 %0, t; }"
        : "=r"(a) : "l"(p));
    return a;
}
__device__ __forceinline__ uint32_t crank() {
    uint32_t r; asm("mov.u32 %0, %%cluster_ctarank;" : "=r"(r)); return r;
}
__device__ __forceinline__ void csync() {
    asm volatile("barrier.cluster.arrive.aligned;" ::: "memory");
    asm volatile("barrier.cluster.wait.aligned;" ::: "memory");
}
__device__ __forceinline__ void fence_g() {
    asm volatile("membar.gl;" ::: "memory");
}
__device__ __forceinline__ float tap(float x) {
    float y; asm("tanh.approx.f32 %0, %1;" : "=f"(y) : "f"(x)); return y;
}
__device__ __forceinline__ float sg(float x) {
    return fmaf(tap(0.5f * x), 0.5f, 0.5f);
}
__device__ __forceinline__ void ldsm4(uint32_t (&d)[4], uint32_t addr) {
    asm volatile("ldmatrix.sync.aligned.m8n8.x4.shared.b16 {%0,%1,%2,%3}, [%4];"
        : "=r"(d[0]), "=r"(d[1]), "=r"(d[2]), "=r"(d[3]) : "r"(addr));
}
__device__ __forceinline__ void hmma(float (&c)[4], const uint32_t (&a)[4],
                                     uint32_t b0, uint32_t b1) {
    asm volatile(
        "mma.sync.aligned.m16n8k16.row.col.f32.f16.f16.f32 "
        "{%0,%1,%2,%3}, {%4,%5,%6,%7}, {%8,%9}, {%0,%1,%2,%3};"
        : "+f"(c[0]), "+f"(c[1]), "+f"(c[2]), "+f"(c[3])
        : "r"(a[0]), "r"(a[1]), "r"(a[2]), "r"(a[3]), "r"(b0), "r"(b1));
}

// K=256 GEMM pass: A = h smem (512B rows, swizzled), B = weight image.
// 16 warps: mt in 0..3 (m16 tile), ch in 0..3 (32-col chunk).
__device__ __forceinline__ void gemm256(float (&acc)[4][4], uint32_t hsm,
                                        uint32_t wsm, int rsh, int kofs,
                                        int mt, int ch, int lane)
{
    const int arow = mt * 16 + ((lane >> 3) & 1) * 8 + (lane & 7);
    const uint32_t rbA = hsm + arow * 512;
    const uint32_t xrA = (uint32_t)((arow & 7) << 4);
    const uint32_t kaA = (uint32_t)(((lane >> 4) & 1) << 4);
    const int nb = ch * 32 + ((lane >> 4) & 1) * 8 + (lane & 7);
    const uint32_t xkB = (uint32_t)(((lane >> 3) & 1) << 4);
    #pragma unroll 4
    for (int kb = 0; kb < 16; kb++) {
        uint32_t a[4];
        ldsm4(a, rbA + ((kb * 32 + kaA) ^ xrA));
        #pragma unroll
        for (int nt = 0; nt < 2; nt++) {
            const int n = nb + nt * 16;
            uint32_t b[4];
            ldsm4(b, wsm + ((uint32_t)n << rsh) +
                     (((uint32_t)((kofs + kb * 16) * 2) + xkB) ^
                      (uint32_t)((n & 7) << 4)));
            hmma(acc[2 * nt],     a, b[0], b[1]);
            hmma(acc[2 * nt + 1], a, b[2], b[3]);
        }
    }
}

// ============================================================================
__global__ void prep_weights(const float* __restrict__ Whh0,
                             const float* __restrict__ Wih1,
                             const float* __restrict__ Whh1,
                             const float* __restrict__ bih1,
                             const float* __restrict__ bhh1)
{
    const int idx = blockIdx.x * blockDim.x + threadIdx.x;
    const int str = gridDim.x * blockDim.x;
    for (int i = idx; i < CSZ * 128 * 256; i += str) {
        const int rk = i >> 15, n = (i >> 8) & 127, k = i & 255;
        const int no = (n & 3) * 256 + rk * 32 + (n >> 2);
        g_W0img[(rk << 15) + (n << 8) + (k ^ ((n & 7) << 3))] =
            __float2half(Whh0[no * 256 + k]);
    }
    for (int i = idx; i < CSZ * 128 * 512; i += str) {
        const int rk = i >> 16, n = (i >> 9) & 127, k = i & 511;
        const int no = (n & 3) * 256 + rk * 32 + (n >> 2);
        const float v = (k < 256) ? Wih1[no * 256 + k]
                                  : Whh1[no * 256 + (k - 256)];
        g_W1img[(rk << 16) + (n << 9) + (k ^ ((n & 7) << 3))] = __float2half(v);
    }
    for (int i = idx; i < CSZ * 128; i += str) {
        const int rk = i >> 7, cc = i & 127;
        const int no = (cc & 3) * 256 + rk * 32 + (cc >> 2);
        g_b1s[i] = bih1[no] + bhh1[no];
    }
    for (int i = idx; i < 2 * HTOT; i += str) g_h1[i] = __half(0.0f);
}

__global__ void prep_gx0(const float* __restrict__ state,
                         const float* __restrict__ gamma,
                         const float* __restrict__ beta,
                         const float* __restrict__ Wih0,
                         const float* __restrict__ bih0,
                         const float* __restrict__ bhh0)
{
    const int b = blockIdx.x, t = threadIdx.x;
    __shared__ float xs[64], xn[64];
    if (t < 64) xs[t] = state[b * 64 + t];
    __syncthreads();
    float mu = 0.f;
    #pragma unroll
    for (int k = 0; k < 64; k++) mu += xs[k];
    mu *= (1.0f / 64.0f);
    float var = 0.f;
    #pragma unroll
    for (int k = 0; k < 64; k++) { float d = xs[k] - mu; var += d * d; }
    const float rs = rsqrtf(var * (1.0f / 64.0f) + 1e-5f);
    if (t < 64) xn[t] = (xs[t] - mu) * rs * gamma[t] + beta[t];
    __syncthreads();
    #pragma unroll
    for (int g = 0; g < 4; g++) {
        const int n = g * 256 + t;
        const float* w = Wih0 + n * 64;
        float acc = bih0[n] + bhh0[n];
        #pragma unroll
        for (int k = 0; k < 64; k++) acc += xn[k] * w[k];
        g_gx0[b * 1024 + t * 4 + g] = acc;
    }
}

// ============================================================================
// 16 clusters x 8 CTAs x 512 thr (16 warps). Identical protocol to the
// passing R12 kernel; only the warp-level decomposition is 2x finer.
// ============================================================================
__global__ void __launch_bounds__(NTH, 1) __cluster_dims__(CSZ, 1, 1)
lstm_mma(const float* __restrict__ fcW, const float* __restrict__ fcb,
         float* __restrict__ out)
{
    extern __shared__ char sm[];
    float* sfcw = (float*)(sm + OFF_FCW);
    float* sb1  = (float*)(sm + OFF_B1);
    const uint32_t w0sm = s2u(sm) + OFF_W0;
    const uint32_t w1sm = s2u(sm) + OFF_W1;
    const uint32_t hsm  = s2u(sm) + OFF_H;

    const int tid = threadIdx.x, wid = tid >> 5, lane = tid & 31;
    const int mt = wid & 3, ch = wid >> 2;           // ch 0..3
    const uint32_t rank = crank();
    const int cid = blockIdx.x >> 3;

    {   // stage weights + constants
        const uint4* s0 = (const uint4*)(g_W0img + ((uint32_t)rank << 15));
        const uint4* s1 = (const uint4*)(g_W1img + ((uint32_t)rank << 16));
        uint4* d0 = (uint4*)sm;
        uint4* d1 = (uint4*)(sm + OFF_W1);
        for (int i = tid; i < 4096; i += NTH) d0[i] = s0[i];
        for (int i = tid; i < 8192; i += NTH) d1[i] = s1[i];
        if (tid < 256) sfcw[tid] = fcW[rank * 256 + tid];
        if (tid < 128) sb1[tid] = g_b1s[rank * 128 + tid];
        uint4 z = make_uint4(0, 0, 0, 0);
        for (int i = tid; i < 2048; i += NTH) ((uint4*)(sm + OFF_H))[i] = z;
    }
    const float fcbv = fcb[rank];

    // per-lane cell geometry: each warp 16 rows x 8 units, 4 cells/thread
    const int cellrow = mt * 16 + (lane >> 2) + ((lane & 1) << 3);
    const int grow = cid * 64 + cellrow;
    const int uloc0 = ch * 8 + ((lane >> 1) & 1);
    float4 gx[4];
    #pragma unroll
    for (int t = 0; t < 4; t++)
        gx[t] = *(const float4*)(g_gx0 + grow * 1024 +
                                 ((int)rank * 32 + uloc0 + 2 * t) * 4);
    float c0r[4], c1r[4];
    #pragma unroll
    for (int t = 0; t < 4; t++) { c0r[t] = 0.f; c1r[t] = 0.f; }

    __half* h0st = g_h0 + grow * 256 + (int)rank * 32 + uloc0;
    const int lr = tid >> 3, lseg = tid & 7;         // 64 rows, 8 segs
    const uint4* h0ld = (const uint4*)(g_h0 + (cid * 64 + lr) * 256 + lseg * 32);

    __syncthreads();

    uint4 hreg[4];
    float acc[4][4];

    for (int s = 0; s < T_; s++) {
        // ---- L0 MMA: gates0 = h0(s-1) @ W0 --------------------------------
        #pragma unroll
        for (int t = 0; t < 4; t++)
            { acc[t][0]=0.f; acc[t][1]=0.f; acc[t][2]=0.f; acc[t][3]=0.f; }
        gemm256(acc, hsm, w0sm, 9, 0, mt, ch, lane);
        // ---- cell0 -> STG h0(s) -------------------------------------------
        #pragma unroll
        for (int t = 0; t < 4; t++) {
            const float s0 = __shfl_xor_sync(0xffffffffu, acc[t][0], 1);
            const float s1 = __shfl_xor_sync(0xffffffffu, acc[t][1], 1);
            const float s2 = __shfl_xor_sync(0xffffffffu, acc[t][2], 1);
            const float s3 = __shfl_xor_sync(0xffffffffu, acc[t][3], 1);
            float gi, gf, gg, go;
            if (lane & 1) { gi = s2; gf = s3; gg = acc[t][2]; go = acc[t][3]; }
            else          { gi = acc[t][0]; gf = acc[t][1]; gg = s0; go = s1; }
            gi += gx[t].x; gf += gx[t].y; gg += gx[t].z; go += gx[t].w;
            const float cn = sg(gf) * c0r[t] + sg(gi) * tap(gg);
            c0r[t] = cn;
            h0st[2 * t] = __float2half(sg(go) * tap(cn));
        }
        fence_g();
        csync();                                 // CS1: h0(s) visible
        fence_g();
        // ---- load full h0(s) -> hreg -> sh --------------------------------
        #pragma unroll
        for (int i = 0; i < 4; i++) hreg[i] = h0ld[i];
        #pragma unroll
        for (int i = 0; i < 4; i++)
            *(uint4*)(sm + OFF_H + lr * 512 +
                      ((lseg * 64 + i * 16) ^ ((lr & 7) << 4))) = hreg[i];
        __syncthreads();
        // ---- L1 part A: h0(s) @ W1[:, 0:256] ------------------------------
        #pragma unroll
        for (int t = 0; t < 4; t++)
            { acc[t][0]=0.f; acc[t][1]=0.f; acc[t][2]=0.f; acc[t][3]=0.f; }
        gemm256(acc, hsm, w1sm, 10, 0, mt, ch, lane);
        __syncthreads();
        // ---- load h1(s-1), FC(s-1), stage h1 into sh ----------------------
        {
            const uint4* h1ld = (const uint4*)(g_h1 + ((s & 1) ^ 1) * HTOT +
                                               (cid * 64 + lr) * 256 + lseg * 32);
            uint4 t1[4];
            #pragma unroll
            for (int i = 0; i < 4; i++) t1[i] = h1ld[i];
            if (s > 0) {
                float f = 0.f;
                #pragma unroll
                for (int i = 0; i < 4; i++) {
                    const __half2* hp = (const __half2*)&t1[i];
                    #pragma unroll
                    for (int j = 0; j < 4; j++) {
                        const float2 h2 = __half22float2(hp[j]);
                        const int kk = lseg * 32 + i * 8 + 2 * j;
                        f += h2.x * sfcw[kk] + h2.y * sfcw[kk + 1];
                    }
                }
                f += __shfl_xor_sync(0xffffffffu, f, 1);
                f += __shfl_xor_sync(0xffffffffu, f, 2);
                f += __shfl_xor_sync(0xffffffffu, f, 4);
                if ((tid & 7) == 0)
                    out[((cid * 64 + lr) * T_ + (s - 1)) * A_ + rank] =
                        tap(f + fcbv);
            }
            #pragma unroll
            for (int i = 0; i < 4; i++)
                *(uint4*)(sm + OFF_H + lr * 512 +
                          ((lseg * 64 + i * 16) ^ ((lr & 7) << 4))) = t1[i];
        }
        __syncthreads();
        // ---- L1 part B: h1(s-1) @ W1[:, 256:512] --------------------------
        gemm256(acc, hsm, w1sm, 10, 256, mt, ch, lane);
        // ---- cell1 -> STG h1(s) (parity buffer) ---------------------------
        __half* h1st = g_h1 + (s & 1) * HTOT + grow * 256 +
                       (int)rank * 32 + uloc0;
        #pragma unroll
        for (int t = 0; t < 4; t++) {
            const float s0 = __shfl_xor_sync(0xffffffffu, acc[t][0], 1);
            const float s1 = __shfl_xor_sync(0xffffffffu, acc[t][1], 1);
            const float s2 = __shfl_xor_sync(0xffffffffu, acc[t][2], 1);
            const float s3 = __shfl_xor_sync(0xffffffffu, acc[t][3], 1);
            float gi, gf, gg, go;
            if (lane & 1) { gi = s2; gf = s3; gg = acc[t][2]; go = acc[t][3]; }
            else          { gi = acc[t][0]; gf = acc[t][1]; gg = s0; go = s1; }
            const float4 bv = *(const float4*)(sb1 + (uloc0 + 2 * t) * 4);
            gi += bv.x; gf += bv.y; gg += bv.z; go += bv.w;
            const float cn = sg(gf) * c1r[t] + sg(gi) * tap(gg);
            c1r[t] = cn;
            h1st[2 * t] = __float2half(sg(go) * tap(cn));
        }
        fence_g();
        csync();                                 // CS2: h1(s) visible
        fence_g();
        // ---- restore h0(s) into sh for next L0 ----------------------------
        #pragma unroll
        for (int i = 0; i < 4; i++)
            *(uint4*)(sm + OFF_H + lr * 512 +
                      ((lseg * 64 + i * 16) ^ ((lr & 7) << 4))) = hreg[i];
        __syncthreads();
    }

    // final FC for step 127 (h1(127) in parity buf 1)
    {
        const uint4* h1ld = (const uint4*)(g_h1 + 1 * HTOT +
                                           (cid * 64 + lr) * 256 + lseg * 32);
        float f = 0.f;
        #pragma unroll
        for (int i = 0; i < 4; i++) {
            const uint4 v = h1ld[i];
            const __half2* hp = (const __half2*)&v;
            #pragma unroll
            for (int j = 0; j < 4; j++) {
                const float2 h2 = __half22float2(hp[j]);
                const int kk = lseg * 32 + i * 8 + 2 * j;
                f += h2.x * sfcw[kk] + h2.y * sfcw[kk + 1];
            }
        }
        f += __shfl_xor_sync(0xffffffffu, f, 1);
        f += __shfl_xor_sync(0xffffffffu, f, 2);
        f += __shfl_xor_sync(0xffffffffu, f, 4);
        if ((tid & 7) == 0)
            out[((cid * 64 + lr) * T_ + 127) * A_ + rank] = tap(f + fcbv);
    }
}

// ============================================================================
extern "C" void kernel_launch(void* const* d_in, const int* in_sizes, int n_in,
                              void* d_out, int out_size)
{
    const float* state = (const float*)d_in[0];
    const float* gamma = (const float*)d_in[1];
    const float* beta  = (const float*)d_in[2];
    const float* Wih0  = (const float*)d_in[3];
    const float* Whh0  = (const float*)d_in[4];
    const float* bih0  = (const float*)d_in[5];
    const float* bhh0  = (const float*)d_in[6];
    const float* Wih1  = (const float*)d_in[7];
    const float* Whh1  = (const float*)d_in[8];
    const float* bih1  = (const float*)d_in[9];
    const float* bhh1  = (const float*)d_in[10];
    const float* fcW   = (const float*)d_in[11];
    const float* fcb   = (const float*)d_in[12];
    float* out = (float*)d_out;

    cudaFuncSetAttribute(lstm_mma, cudaFuncAttributeMaxDynamicSharedMemorySize,
                         SMEMB);
    prep_weights<<<264, 256>>>(Whh0, Wih1, Whh1, bih1, bhh1);
    prep_gx0<<<1024, 256>>>(state, gamma, beta, Wih0, bih0, bhh0);
    lstm_mma<<<NCL * CSZ, NTH, SMEMB>>>(fcW, fcb, out);
}